// round 12
// baseline (speedup 1.0000x reference)
#include <cuda_runtime.h>
#include <cuda_bf16.h>
#include <cstdint>

#define BATCH 4096
#define DIM   512
#define HIDN  2048
#define NSTEPS 20

#define BM 64
#define BN 128
#define BK 32
#define MI 2
#define NI 4
#define SPITCH 40          // bf16 per smem row (80B) — 16B-aligned, LDSM conflict-free
#define ROWB (SPITCH*2)

#define ASZ (BM*ROWB)      // 5120
#define BSZ (BN*ROWB)      // 10240
#define SMA 1024
#define SMB (SMA + 4*ASZ)
#define SMEM_TOT (SMB + 4*BSZ)   // 62464  (x3 CTAs = 187.4KB <= 227KB)

// ---------------- persistent scratch ----------------
__device__ __align__(256) float          g_zcur[BATCH*DIM];
__device__ __align__(256) float          g_zacc[BATCH*DIM];
__device__ __align__(256) float          g_kp[4][BATCH*DIM];   // split-K partials
__device__ __align__(256) __nv_bfloat16  g_zb[BATCH*DIM];
__device__ __align__(256) __nv_bfloat16  g_hid[BATCH*HIDN];
__device__ __align__(256) __nv_bfloat16  g_w1t[HIDN*DIM];      // [n][k]
__device__ __align__(256) float          g_w1last[HIDN];
__device__ __align__(256) __nv_bfloat16  g_w2t[DIM*HIDN];      // [n][k]

// ---------------- converts ----------------
__global__ void convert_z(const float* __restrict__ z0){
    int i = blockIdx.x*blockDim.x + threadIdx.x;
    if (i < BATCH*DIM){
        float v = z0[i];
        g_zcur[i] = v;
        g_zb[i]   = __float2bfloat16(v);
    }
}
__global__ void convert_w(const float* __restrict__ W1, const float* __restrict__ W2){
    int i = blockIdx.x*blockDim.x + threadIdx.x;
    if (i < HIDN*DIM){
        int n = i / DIM, k = i % DIM;
        g_w1t[i] = __float2bfloat16(W1[(size_t)k*HIDN + n]);
    }
    if (i < DIM*HIDN){
        int n = i / HIDN, k = i % HIDN;
        g_w2t[i] = __float2bfloat16(W2[(size_t)k*DIM + n]);
    }
    if (i < HIDN) g_w1last[i] = W1[(size_t)DIM*HIDN + i];
}

// ---------------- helpers ----------------
__device__ __forceinline__ void cpa16(uint32_t s, const void* g){
    asm volatile("cp.async.cg.shared.global [%0], [%1], 16;\n" :: "r"(s), "l"(g));
}
__device__ __forceinline__ void ldsm4(uint32_t& r0, uint32_t& r1, uint32_t& r2, uint32_t& r3,
                                      uint32_t addr){
    asm volatile("ldmatrix.sync.aligned.m8n8.x4.shared.b16 {%0,%1,%2,%3}, [%4];"
                 : "=r"(r0), "=r"(r1), "=r"(r2), "=r"(r3) : "r"(addr));
}
__device__ __forceinline__ uint32_t smem_u32(const void* p){
    uint32_t a;
    asm("{ .reg .u64 t; cvta.to.shared.u64 t, %1; cvt.u32.u64 %0, t; }" : "=r"(a) : "l"(p));
    return a;
}
#define MMA16816(acc, af, bf)                                                     \
    asm volatile(                                                                 \
        "mma.sync.aligned.m16n8k16.row.col.f32.bf16.bf16.f32 "                    \
        "{%0,%1,%2,%3}, {%4,%5,%6,%7}, {%8,%9}, {%0,%1,%2,%3};\n"                 \
        : "+f"(acc[0]), "+f"(acc[1]), "+f"(acc[2]), "+f"(acc[3])                  \
        : "r"(af[0]), "r"(af[1]), "r"(af[2]), "r"(af[3]), "r"(bf[0]), "r"(bf[1]))

// ---------------- fused GEMM ----------------
// CTA 64x128, 256 thr (8 warps: 2M x 4N, warp 32x32), BK=32, 4-stage (3 in flight),
// K-extent 512 per launch.
// epi==0: g_hid = tanh(g_zb @ g_w1t^T + b1 + t*w1last)
// epi==1: g_kp[blockIdx.z] = partial(g_hid @ g_w2t^T), K = [z*512, z*512+512)
__global__ void __launch_bounds__(256, 3)
gemm_tc(const float* __restrict__ b1,
        const float* __restrict__ t0p, const float* __restrict__ t1p,
        int epi, float stepF, float cOff)
{
    extern __shared__ char smem[];
    const uint32_t sb = smem_u32(smem);
    float* biasS = (float*)smem;

    const int tid  = threadIdx.x;
    const int lane = tid & 31, w = tid >> 5;
    const int bm = blockIdx.y * BM, bn = blockIdx.x * BN;

    const __nv_bfloat16* A; const __nv_bfloat16* B; int Kd, kOff;
    float* kp = nullptr;
    if (epi == 0){ A = g_zb;  B = g_w1t; Kd = DIM;  kOff = 0; }
    else {
        A = g_hid; B = g_w2t; Kd = HIDN;
        kOff = blockIdx.z * 512;
        kp   = g_kp[blockIdx.z];
    }
    constexpr int NT = 512 / BK;    // 16 for both paths

    const int wm = (w >> 2) * 32;
    const int wn = (w & 3)  * 32;

    const int lr = lane & 7;
    const int lm = (lane >> 3) & 1;
    const int lk = (lane >> 4) & 1;
    const uint32_t aBase = sb + SMA + (uint32_t)((wm + lr + lm*8)*SPITCH + lk*8)*2;
    const uint32_t bBase = sb + SMB + (uint32_t)((wn + lr + lm*8)*SPITCH + lk*8)*2;

    auto loadChunk = [&](int c){
        const int s  = c & 3;
        const int k0 = kOff + c * BK;
        const uint32_t sA = sb + SMA + s*ASZ;
        const uint32_t sB = sb + SMB + s*BSZ;
        {   // A: 64 rows x 4 x 16B = 256 vectors (1 per thread)
            int row = tid >> 2, col = tid & 3;
            cpa16(sA + row*ROWB + col*16, A + (size_t)(bm + row)*Kd + k0 + col*8);
        }
        #pragma unroll
        for (int r = 0; r < 2; r++){   // B: 128 rows x 4 x 16B = 512 vectors
            int v = tid + r*256;
            int row = v >> 2, col = v & 3;
            cpa16(sB + row*ROWB + col*16, B + (size_t)(bn + row)*Kd + k0 + col*8);
        }
        asm volatile("cp.async.commit_group;\n");
    };

    loadChunk(0);
    loadChunk(1);
    loadChunk(2);

    // bias -> smem (GEMM1 only)
    if (epi == 0 && tid < BN){
        const float t0v = __ldg(t0p), t1v = __ldg(t1p);
        const float hh  = (t1v - t0v) / (float)NSTEPS;
        float t = t0v + (stepF + cOff) * hh;
        biasS[tid] = __ldg(&b1[bn + tid]) + t * g_w1last[bn + tid];
    }

    float acc[MI][NI][4];
    #pragma unroll
    for (int a=0;a<MI;a++)
        #pragma unroll
        for (int b=0;b<NI;b++)
            #pragma unroll
            for (int c=0;c<4;c++) acc[a][b][c] = 0.f;

    for (int kt = 0; kt < NT; kt++){
        if      (kt < NT-2) asm volatile("cp.async.wait_group 2;\n");
        else if (kt == NT-2) asm volatile("cp.async.wait_group 1;\n");
        else                 asm volatile("cp.async.wait_group 0;\n");
        __syncthreads();
        if (kt + 3 < NT) loadChunk(kt + 3);   // stage (kt+3)&3 == (kt-1)&3: safe after sync

        const int s = kt & 3;
        const uint32_t aAddr = aBase + s*ASZ;
        const uint32_t bAddr = bBase + s*BSZ;

        #pragma unroll
        for (int kki = 0; kki < 2; kki++){
            const uint32_t koff = (uint32_t)(kki*32);   // 16 bf16 = 32B
            uint32_t af[MI][4], bf[NI][2];
            #pragma unroll
            for (int mi = 0; mi < MI; mi++)
                ldsm4(af[mi][0], af[mi][1], af[mi][2], af[mi][3],
                      aAddr + (uint32_t)(mi*16*ROWB) + koff);
            #pragma unroll
            for (int nh = 0; nh < NI/2; nh++){
                uint32_t r0, r1, r2, r3;
                ldsm4(r0, r1, r2, r3, bAddr + (uint32_t)(nh*16*ROWB) + koff);
                bf[2*nh  ][0] = r0; bf[2*nh  ][1] = r2;
                bf[2*nh+1][0] = r1; bf[2*nh+1][1] = r3;
            }
            #pragma unroll
            for (int mi = 0; mi < MI; mi++)
                #pragma unroll
                for (int ni = 0; ni < NI; ni++)
                    MMA16816(acc[mi][ni], af[mi], bf[ni]);
        }
    }

    // ---------------- epilogue ----------------
    const int g  = lane >> 2;
    const int tq = lane & 3;

    #pragma unroll
    for (int mi = 0; mi < MI; mi++)
        #pragma unroll
        for (int ni = 0; ni < NI; ni++){
            const int colL = wn + ni*8 + tq*2;
            const int col  = bn + colL;
            #pragma unroll
            for (int half = 0; half < 2; half++){
                const int row = bm + wm + mi*16 + g + half*8;
                float v0 = acc[mi][ni][half*2+0];
                float v1 = acc[mi][ni][half*2+1];
                if (epi == 0){
                    v0 += biasS[colL]; v1 += biasS[colL+1];
                    float th0, th1;
                    asm("tanh.approx.f32 %0, %1;" : "=f"(th0) : "f"(v0));
                    asm("tanh.approx.f32 %0, %1;" : "=f"(th1) : "f"(v1));
                    *(__nv_bfloat162*)(&g_hid[(size_t)row*HIDN + col]) =
                        __floats2bfloat162_rn(th0, th1);
                } else {
                    *(float2*)(&kp[(size_t)row*DIM + col]) = make_float2(v0, v1);
                }
            }
        }
}

// ---------------- RK4 elementwise update ----------------
__global__ void __launch_bounds__(256)
rk4_update(const float* __restrict__ b2,
           const float* __restrict__ t0p, const float* __restrict__ t1p,
           float* __restrict__ dout,
           float wcoef, float acoef, int accPrev, int finalStage, int toOut)
{
    const int i4 = blockIdx.x*256 + threadIdx.x;
    const int base = i4 * 4;
    const float hh = (__ldg(t1p) - __ldg(t0p)) / (float)NSTEPS;
    const float wh = wcoef * hh, ah = acoef * hh;

    float4 k0 = *(const float4*)(&g_kp[0][base]);
    float4 k1 = *(const float4*)(&g_kp[1][base]);
    float4 k2 = *(const float4*)(&g_kp[2][base]);
    float4 k3 = *(const float4*)(&g_kp[3][base]);
    const float4 bb = *(const float4*)(&b2[base & (DIM-1)]);
    float4 k = make_float4(k0.x+k1.x+k2.x+k3.x+bb.x,
                           k0.y+k1.y+k2.y+k3.y+bb.y,
                           k0.z+k1.z+k2.z+k3.z+bb.z,
                           k0.w+k1.w+k2.w+k3.w+bb.w);

    float4 za;
    if (accPrev) za = *(const float4*)(&g_zacc[base]);
    else         za = make_float4(0.f,0.f,0.f,0.f);
    za.x += wh*k.x; za.y += wh*k.y; za.z += wh*k.z; za.w += wh*k.w;
    *(float4*)(&g_zacc[base]) = za;

    float4 zc = *(const float4*)(&g_zcur[base]);
    float4 zn;
    if (finalStage){
        zn = make_float4(zc.x+za.x, zc.y+za.y, zc.z+za.z, zc.w+za.w);
        if (toOut) *(float4*)(&dout[base]) = zn;
        else       *(float4*)(&g_zcur[base]) = zn;
    } else {
        zn = make_float4(zc.x+ah*k.x, zc.y+ah*k.y, zc.z+ah*k.z, zc.w+ah*k.w);
    }
    *(__nv_bfloat162*)(&g_zb[base])   = __floats2bfloat162_rn(zn.x, zn.y);
    *(__nv_bfloat162*)(&g_zb[base+2]) = __floats2bfloat162_rn(zn.z, zn.w);
}

// ---------------- launcher ----------------
extern "C" void kernel_launch(void* const* d_in, const int* in_sizes, int n_in,
                              void* d_out, int out_size)
{
    const float* z0 = (const float*)d_in[0];
    const float* W1 = (const float*)d_in[1];
    const float* b1 = (const float*)d_in[2];
    const float* W2 = (const float*)d_in[3];
    const float* b2 = (const float*)d_in[4];
    const float* t0 = (const float*)d_in[5];
    const float* t1 = (const float*)d_in[6];
    float* dout = (float*)d_out;
    (void)in_sizes; (void)n_in; (void)out_size;

    cudaFuncSetAttribute(gemm_tc, cudaFuncAttributeMaxDynamicSharedMemorySize, SMEM_TOT);

    convert_z<<<(BATCH*DIM + 255)/256, 256>>>(z0);
    convert_w<<<(HIDN*DIM + 255)/256, 256>>>(W1, W2);

    dim3 gH(HIDN/BN, BATCH/BM, 1);   // 16 x 64      = 1024 CTAs
    dim3 gK(DIM/BN,  BATCH/BM, 4);   //  4 x 64 x 4  = 1024 CTAs (split-K=4)
    const int gE = (BATCH*DIM/4 + 255)/256;  // 2048 CTAs

    const float Wc[4]   = {1.f/6.f, 1.f/3.f, 1.f/3.f, 1.f/6.f};
    const float Ac[4]   = {0.5f, 0.5f, 1.0f, 0.f};
    const float Coff[4] = {0.f, 0.5f, 0.5f, 1.0f};

    for (int i = 0; i < NSTEPS; i++){
        for (int s = 0; s < 4; s++){
            gemm_tc<<<gH, 256, SMEM_TOT>>>(b1, t0, t1, 0, (float)i, Coff[s]);
            gemm_tc<<<gK, 256, SMEM_TOT>>>(b1, t0, t1, 1, (float)i, 0.f);
            const int fin  = (s == 3);
            const int tOut = (fin && i == NSTEPS-1);
            rk4_update<<<gE, 256>>>(b2, t0, t1, dout,
                                    Wc[s], Ac[s], (s > 0), fin, tOut);
        }
    }
}

// round 13
// speedup vs baseline: 1.0673x; 1.0673x over previous
#include <cuda_runtime.h>
#include <cuda_bf16.h>
#include <cstdint>

#define BATCH 4096
#define DIM   512
#define HIDN  2048
#define NSTEPS 20

#define BM 64
#define BN 128
#define BK 32
#define MI 2
#define NI 4
#define SPITCH 40          // bf16 per smem row (80B) — 16B-aligned, LDSM conflict-free
#define ROWB (SPITCH*2)

#define ASZ (BM*ROWB)      // 5120
#define BSZ (BN*ROWB)      // 10240
#define SMA 1024
#define SMB (SMA + 3*ASZ)
#define SMEM_TOT (SMB + 3*BSZ)   // 47104

// ---------------- persistent scratch ----------------
__device__ __align__(256) float          g_zcur[BATCH*DIM];
__device__ __align__(256) float          g_zacc[BATCH*DIM];
__device__ __align__(256) __nv_bfloat16  g_kp[4][BATCH*DIM];   // split-K partials (bf16)
__device__ __align__(256) __nv_bfloat16  g_zb[BATCH*DIM];
__device__ __align__(256) __nv_bfloat16  g_hid[BATCH*HIDN];
__device__ __align__(256) __nv_bfloat16  g_w1t[HIDN*DIM];      // [n][k]
__device__ __align__(256) float          g_w1last[HIDN];
__device__ __align__(256) __nv_bfloat16  g_w2t[DIM*HIDN];      // [n][k]

// ---------------- converts ----------------
__global__ void convert_z(const float* __restrict__ z0){
    int i = blockIdx.x*blockDim.x + threadIdx.x;
    if (i < BATCH*DIM){
        float v = z0[i];
        g_zcur[i] = v;
        g_zb[i]   = __float2bfloat16(v);
    }
}
__global__ void convert_w(const float* __restrict__ W1, const float* __restrict__ W2){
    int i = blockIdx.x*blockDim.x + threadIdx.x;
    if (i < HIDN*DIM){
        int n = i / DIM, k = i % DIM;
        g_w1t[i] = __float2bfloat16(W1[(size_t)k*HIDN + n]);
    }
    if (i < DIM*HIDN){
        int n = i / HIDN, k = i % HIDN;
        g_w2t[i] = __float2bfloat16(W2[(size_t)k*DIM + n]);
    }
    if (i < HIDN) g_w1last[i] = W1[(size_t)DIM*HIDN + i];
}

// ---------------- helpers ----------------
__device__ __forceinline__ void cpa16(uint32_t s, const void* g){
    asm volatile("cp.async.cg.shared.global [%0], [%1], 16;\n" :: "r"(s), "l"(g));
}
__device__ __forceinline__ void ldsm4(uint32_t& r0, uint32_t& r1, uint32_t& r2, uint32_t& r3,
                                      uint32_t addr){
    asm volatile("ldmatrix.sync.aligned.m8n8.x4.shared.b16 {%0,%1,%2,%3}, [%4];"
                 : "=r"(r0), "=r"(r1), "=r"(r2), "=r"(r3) : "r"(addr));
}
__device__ __forceinline__ uint32_t smem_u32(const void* p){
    uint32_t a;
    asm("{ .reg .u64 t; cvta.to.shared.u64 t, %1; cvt.u32.u64 %0, t; }" : "=r"(a) : "l"(p));
    return a;
}
#define MMA16816(acc, af, bf)                                                     \
    asm volatile(                                                                 \
        "mma.sync.aligned.m16n8k16.row.col.f32.bf16.bf16.f32 "                    \
        "{%0,%1,%2,%3}, {%4,%5,%6,%7}, {%8,%9}, {%0,%1,%2,%3};\n"                 \
        : "+f"(acc[0]), "+f"(acc[1]), "+f"(acc[2]), "+f"(acc[3])                  \
        : "r"(af[0]), "r"(af[1]), "r"(af[2]), "r"(af[3]), "r"(bf[0]), "r"(bf[1]))

// ---------------- fused GEMM (R9 structure) ----------------
// CTA 64x128, 256 thr (8 warps: 2M x 4N, warp 32x32), BK=32, 3-stage, K-extent 512.
// epi==0: g_hid = tanh(g_zb @ g_w1t^T + b1 + t*w1last)
// epi==1: g_kp[blockIdx.z] = bf16 partial(g_hid @ g_w2t^T), K = [z*512, z*512+512)
__global__ void __launch_bounds__(256, 3)
gemm_tc(const float* __restrict__ b1,
        const float* __restrict__ t0p, const float* __restrict__ t1p,
        int epi, float stepF, float cOff)
{
    extern __shared__ char smem[];
    const uint32_t sb = smem_u32(smem);
    float* biasS = (float*)smem;

    const int tid  = threadIdx.x;
    const int lane = tid & 31, w = tid >> 5;
    const int bm = blockIdx.y * BM, bn = blockIdx.x * BN;

    const __nv_bfloat16* A; const __nv_bfloat16* B; int Kd, kOff;
    __nv_bfloat16* kp = nullptr;
    if (epi == 0){ A = g_zb;  B = g_w1t; Kd = DIM;  kOff = 0; }
    else {
        A = g_hid; B = g_w2t; Kd = HIDN;
        kOff = blockIdx.z * 512;
        kp   = g_kp[blockIdx.z];
    }
    constexpr int NT = 512 / BK;    // 16 for both paths

    const int wm = (w >> 2) * 32;
    const int wn = (w & 3)  * 32;

    const int lr = lane & 7;
    const int lm = (lane >> 3) & 1;
    const int lk = (lane >> 4) & 1;
    const uint32_t aBase = sb + SMA + (uint32_t)((wm + lr + lm*8)*SPITCH + lk*8)*2;
    const uint32_t bBase = sb + SMB + (uint32_t)((wn + lr + lm*8)*SPITCH + lk*8)*2;

    auto loadChunk = [&](int c){
        const int s  = c % 3;
        const int k0 = kOff + c * BK;
        const uint32_t sA = sb + SMA + s*ASZ;
        const uint32_t sB = sb + SMB + s*BSZ;
        {   // A: 64 rows x 4 x 16B = 256 vectors (1 per thread)
            int row = tid >> 2, col = tid & 3;
            cpa16(sA + row*ROWB + col*16, A + (size_t)(bm + row)*Kd + k0 + col*8);
        }
        #pragma unroll
        for (int r = 0; r < 2; r++){   // B: 128 rows x 4 x 16B = 512 vectors
            int v = tid + r*256;
            int row = v >> 2, col = v & 3;
            cpa16(sB + row*ROWB + col*16, B + (size_t)(bn + row)*Kd + k0 + col*8);
        }
        asm volatile("cp.async.commit_group;\n");
    };

    loadChunk(0);
    loadChunk(1);

    // bias -> smem (GEMM1 only)
    if (epi == 0 && tid < BN){
        const float t0v = __ldg(t0p), t1v = __ldg(t1p);
        const float hh  = (t1v - t0v) / (float)NSTEPS;
        float t = t0v + (stepF + cOff) * hh;
        biasS[tid] = __ldg(&b1[bn + tid]) + t * g_w1last[bn + tid];
    }

    float acc[MI][NI][4];
    #pragma unroll
    for (int a=0;a<MI;a++)
        #pragma unroll
        for (int b=0;b<NI;b++)
            #pragma unroll
            for (int c=0;c<4;c++) acc[a][b][c] = 0.f;

    for (int kt = 0; kt < NT; kt++){
        if (kt < NT-1) asm volatile("cp.async.wait_group 1;\n");
        else           asm volatile("cp.async.wait_group 0;\n");
        __syncthreads();
        if (kt + 2 < NT) loadChunk(kt + 2);   // writes stage (kt+2)%3 == (kt-1)%3: safe after sync

        const int s = kt % 3;
        const uint32_t aAddr = aBase + s*ASZ;
        const uint32_t bAddr = bBase + s*BSZ;

        #pragma unroll
        for (int kki = 0; kki < 2; kki++){
            const uint32_t koff = (uint32_t)(kki*32);   // 16 bf16 = 32B
            uint32_t af[MI][4], bf[NI][2];
            #pragma unroll
            for (int mi = 0; mi < MI; mi++)
                ldsm4(af[mi][0], af[mi][1], af[mi][2], af[mi][3],
                      aAddr + (uint32_t)(mi*16*ROWB) + koff);
            #pragma unroll
            for (int nh = 0; nh < NI/2; nh++){
                uint32_t r0, r1, r2, r3;
                ldsm4(r0, r1, r2, r3, bAddr + (uint32_t)(nh*16*ROWB) + koff);
                bf[2*nh  ][0] = r0; bf[2*nh  ][1] = r2;
                bf[2*nh+1][0] = r1; bf[2*nh+1][1] = r3;
            }
            #pragma unroll
            for (int mi = 0; mi < MI; mi++)
                #pragma unroll
                for (int ni = 0; ni < NI; ni++)
                    MMA16816(acc[mi][ni], af[mi], bf[ni]);
        }
    }

    // ---------------- epilogue ----------------
    const int g  = lane >> 2;
    const int tq = lane & 3;

    #pragma unroll
    for (int mi = 0; mi < MI; mi++)
        #pragma unroll
        for (int ni = 0; ni < NI; ni++){
            const int colL = wn + ni*8 + tq*2;
            const int col  = bn + colL;
            #pragma unroll
            for (int half = 0; half < 2; half++){
                const int row = bm + wm + mi*16 + g + half*8;
                float v0 = acc[mi][ni][half*2+0];
                float v1 = acc[mi][ni][half*2+1];
                if (epi == 0){
                    v0 += biasS[colL]; v1 += biasS[colL+1];
                    float th0, th1;
                    asm("tanh.approx.f32 %0, %1;" : "=f"(th0) : "f"(v0));
                    asm("tanh.approx.f32 %0, %1;" : "=f"(th1) : "f"(v1));
                    *(__nv_bfloat162*)(&g_hid[(size_t)row*HIDN + col]) =
                        __floats2bfloat162_rn(th0, th1);
                } else {
                    *(__nv_bfloat162*)(&kp[(size_t)row*DIM + col]) =
                        __floats2bfloat162_rn(v0, v1);
                }
            }
        }
}

// ---------------- RK4 elementwise update ----------------
// k = sum_z kp[z] + b2[col]; zacc += wh*k;
// finalStage: zn = zcur + zacc -> zcur/dout ; else zn = zcur + ah*k ; zb = bf16(zn)
__global__ void __launch_bounds__(256)
rk4_update(const float* __restrict__ b2,
           const float* __restrict__ t0p, const float* __restrict__ t1p,
           float* __restrict__ dout,
           float wcoef, float acoef, int accPrev, int finalStage, int toOut)
{
    const int i4 = blockIdx.x*256 + threadIdx.x;
    const int base = i4 * 4;
    const float hh = (__ldg(t1p) - __ldg(t0p)) / (float)NSTEPS;
    const float wh = wcoef * hh, ah = acoef * hh;

    // load 4 bf16 partials x 4 elements (8B each)
    float kx, ky, kz, kw;
    {
        const float4 bb = *(const float4*)(&b2[base & (DIM-1)]);
        kx = bb.x; ky = bb.y; kz = bb.z; kw = bb.w;
        #pragma unroll
        for (int z = 0; z < 4; z++){
            const __nv_bfloat162* p = (const __nv_bfloat162*)(&g_kp[z][base]);
            float2 lo = __bfloat1622float2(p[0]);
            float2 hi = __bfloat1622float2(p[1]);
            kx += lo.x; ky += lo.y; kz += hi.x; kw += hi.y;
        }
    }

    float4 za;
    if (accPrev) za = *(const float4*)(&g_zacc[base]);
    else         za = make_float4(0.f,0.f,0.f,0.f);
    za.x += wh*kx; za.y += wh*ky; za.z += wh*kz; za.w += wh*kw;
    *(float4*)(&g_zacc[base]) = za;

    float4 zc = *(const float4*)(&g_zcur[base]);
    float4 zn;
    if (finalStage){
        zn = make_float4(zc.x+za.x, zc.y+za.y, zc.z+za.z, zc.w+za.w);
        if (toOut) *(float4*)(&dout[base]) = zn;
        else       *(float4*)(&g_zcur[base]) = zn;
    } else {
        zn = make_float4(zc.x+ah*kx, zc.y+ah*ky, zc.z+ah*kz, zc.w+ah*kw);
    }
    *(__nv_bfloat162*)(&g_zb[base])   = __floats2bfloat162_rn(zn.x, zn.y);
    *(__nv_bfloat162*)(&g_zb[base+2]) = __floats2bfloat162_rn(zn.z, zn.w);
}

// ---------------- launcher ----------------
extern "C" void kernel_launch(void* const* d_in, const int* in_sizes, int n_in,
                              void* d_out, int out_size)
{
    const float* z0 = (const float*)d_in[0];
    const float* W1 = (const float*)d_in[1];
    const float* b1 = (const float*)d_in[2];
    const float* W2 = (const float*)d_in[3];
    const float* b2 = (const float*)d_in[4];
    const float* t0 = (const float*)d_in[5];
    const float* t1 = (const float*)d_in[6];
    float* dout = (float*)d_out;
    (void)in_sizes; (void)n_in; (void)out_size;

    cudaFuncSetAttribute(gemm_tc, cudaFuncAttributeMaxDynamicSharedMemorySize, SMEM_TOT);

    convert_z<<<(BATCH*DIM + 255)/256, 256>>>(z0);
    convert_w<<<(HIDN*DIM + 255)/256, 256>>>(W1, W2);

    dim3 gH(HIDN/BN, BATCH/BM, 1);   // 16 x 64      = 1024 CTAs
    dim3 gK(DIM/BN,  BATCH/BM, 4);   //  4 x 64 x 4  = 1024 CTAs (split-K=4)
    const int gE = (BATCH*DIM/4 + 255)/256;  // 2048 CTAs

    const float Wc[4]   = {1.f/6.f, 1.f/3.f, 1.f/3.f, 1.f/6.f};
    const float Ac[4]   = {0.5f, 0.5f, 1.0f, 0.f};
    const float Coff[4] = {0.f, 0.5f, 0.5f, 1.0f};

    for (int i = 0; i < NSTEPS; i++){
        for (int s = 0; s < 4; s++){
            gemm_tc<<<gH, 256, SMEM_TOT>>>(b1, t0, t1, 0, (float)i, Coff[s]);
            gemm_tc<<<gK, 256, SMEM_TOT>>>(b1, t0, t1, 1, (float)i, 0.f);
            const int fin  = (s == 3);
            const int tOut = (fin && i == NSTEPS-1);
            rk4_update<<<gE, 256>>>(b2, t0, t1, dout,
                                    Wc[s], Ac[s], (s > 0), fin, tOut);
        }
    }
}